// round 6
// baseline (speedup 1.0000x reference)
#include <cuda_runtime.h>
#include <cstdint>

#define NN 100000
#define NE 1600000
#define NCH 64
#define EPS 1e-5f
#define SCAN_BLK 1024
#define NB1 ((NN + SCAN_BLK - 1) / SCAN_BLK)   // 98
#define GB  ((NN + 127) / 128)                 // 782 gemm blocks

// ---------------- scratch (device globals; no allocation allowed) ----------
__device__ int   g_deg[NN];
__device__ float g_dinv[NN];
__device__ int   g_off[NN + 1];
__device__ int   g_cur[NN];
__device__ int   g_bsum[NB1];
__device__ int2  g_csr[NE];                    // {src, w bits}
__device__ float g_Tx1[(size_t)NN * NCH];
__device__ float g_Tx2[(size_t)NN * NCH];
__device__ float g_Y[(size_t)NN * NCH];
__device__ float g_part[2 * GB * NCH];
__device__ float g_stats[2 * NCH];

// ---------------- degree ---------------------------------------------------
__global__ void k_zero_deg() {
    int i = blockIdx.x * blockDim.x + threadIdx.x;
    if (i < NN) g_deg[i] = 0;
}

// edge_index is int32 (JAX default x64-disabled demotes int64 -> int32)
__global__ void k_deg(const int* __restrict__ ei) {
    int i = blockIdx.x * blockDim.x + threadIdx.x;
    if (i < NE / 4) {
        int4 d = ((const int4*)(ei + NE))[i];
        if ((unsigned)d.x < NN) atomicAdd(&g_deg[d.x], 1);
        if ((unsigned)d.y < NN) atomicAdd(&g_deg[d.y], 1);
        if ((unsigned)d.z < NN) atomicAdd(&g_deg[d.z], 1);
        if ((unsigned)d.w < NN) atomicAdd(&g_deg[d.w], 1);
    }
}

// ---------------- prefix sum (3-phase), dinv fused into phase 1 ------------
__global__ void k_scan1() {
    __shared__ int sh[SCAN_BLK];
    int tid = threadIdx.x;
    int i = blockIdx.x * SCAN_BLK + tid;
    int v = 0;
    if (i < NN) {
        v = g_deg[i];
        g_dinv[i] = (v > 0) ? rsqrtf((float)v) : 0.0f;
    }
    sh[tid] = v;
    __syncthreads();
    for (int ofs = 1; ofs < SCAN_BLK; ofs <<= 1) {
        int t = (tid >= ofs) ? sh[tid - ofs] : 0;
        __syncthreads();
        sh[tid] += t;
        __syncthreads();
    }
    if (i < NN) g_off[i + 1] = sh[tid];       // local inclusive
    if (tid == SCAN_BLK - 1) g_bsum[blockIdx.x] = sh[tid];
}

// parallel exclusive scan over NB1 (=98) block sums, 128 threads
__global__ void k_scan2() {
    __shared__ int sh[128];
    int tid = threadIdx.x;
    int v = (tid < NB1) ? g_bsum[tid] : 0;
    sh[tid] = v;
    __syncthreads();
    for (int ofs = 1; ofs < 128; ofs <<= 1) {
        int t = (tid >= ofs) ? sh[tid - ofs] : 0;
        __syncthreads();
        sh[tid] += t;
        __syncthreads();
    }
    if (tid < NB1) g_bsum[tid] = sh[tid] - v; // exclusive
}

// phase 3 + cur init fused: final off[i+1] is also cur[i+1]
__global__ void k_scan3() {
    int i = blockIdx.x * blockDim.x + threadIdx.x;
    if (i < NN) {
        int fin = g_off[i + 1] + g_bsum[i / SCAN_BLK];
        g_off[i + 1] = fin;
        if (i + 1 < NN) g_cur[i + 1] = fin;
    }
    if (i == 0) { g_off[0] = 0; g_cur[0] = 0; }
}

// ---------------- counting-sort edges into CSR by dst ----------------------
__global__ void k_fill(const int* __restrict__ ei) {
    int e = blockIdx.x * blockDim.x + threadIdx.x;
    if (e < NE) {
        int s = ei[e];
        int d = ei[NE + e];
        if ((unsigned)s < NN && (unsigned)d < NN) {
            float w = -g_dinv[s] * g_dinv[d];
            int pos = atomicAdd(&g_cur[d], 1);
            if ((unsigned)pos < NE)
                g_csr[pos] = make_int2(s, __float_as_int(w));
        }
    }
}

// ---------------- sparse propagation: one warp per dst node ----------------
// Half-warp per edge; lane covers 16B (float4) of the 256B row.
// MODE 0: h=xp,  o=Tx1                MODE 1: h=Tx1, o=Tx2, sub=xp
// MODE 2: h=norm(g_Y), o=Tx1          MODE 3: h=Tx1, o=Tx2, sub=norm(g_Y)
// MODE 2 normalization is algebraic: r*acc - (m*r)*sum_w (no per-edge cost).
template <int MODE>
__global__ void k_prop(const float* __restrict__ xp) {
    const float* h;
    float* o;
    if (MODE == 0) { h = xp;    o = g_Tx1; }
    if (MODE == 1) { h = g_Tx1; o = g_Tx2; }
    if (MODE == 2) { h = g_Y;   o = g_Tx1; }
    if (MODE == 3) { h = g_Tx1; o = g_Tx2; }

    int node = blockIdx.x * (blockDim.x >> 5) + (threadIdx.x >> 5);
    if (node >= NN) return;
    int lane = threadIdx.x & 31;
    int half = lane >> 4;
    int q4 = (lane & 15) * 4;
    int beg = g_off[node], end = g_off[node + 1];

    float4 m4, r4;
    if (MODE == 2 || MODE == 3) {
        m4 = *(const float4*)(g_stats + q4);
        r4 = *(const float4*)(g_stats + 64 + q4);
    }

    float4 acc = make_float4(0.f, 0.f, 0.f, 0.f);
    float wsum = 0.f;
    int j = beg;
    for (; j + 7 < end; j += 8) {
        int2 ea = g_csr[j + half];
        int2 eb = g_csr[j + 2 + half];
        int2 ec = g_csr[j + 4 + half];
        int2 ed = g_csr[j + 6 + half];
        const float4 va = *(const float4*)(h + (size_t)ea.x * NCH + q4);
        const float4 vb = *(const float4*)(h + (size_t)eb.x * NCH + q4);
        const float4 vc = *(const float4*)(h + (size_t)ec.x * NCH + q4);
        const float4 vd = *(const float4*)(h + (size_t)ed.x * NCH + q4);
        float wa = __int_as_float(ea.y), wb = __int_as_float(eb.y);
        float wc = __int_as_float(ec.y), wd = __int_as_float(ed.y);
        acc.x += wa * va.x + wb * vb.x + wc * vc.x + wd * vd.x;
        acc.y += wa * va.y + wb * vb.y + wc * vc.y + wd * vd.y;
        acc.z += wa * va.z + wb * vb.z + wc * vc.z + wd * vd.z;
        acc.w += wa * va.w + wb * vb.w + wc * vc.w + wd * vd.w;
        if (MODE == 2) wsum += wa + wb + wc + wd;
    }
    for (; j + 3 < end; j += 4) {
        int2 ea = g_csr[j + half];
        int2 eb = g_csr[j + 2 + half];
        const float4 va = *(const float4*)(h + (size_t)ea.x * NCH + q4);
        const float4 vb = *(const float4*)(h + (size_t)eb.x * NCH + q4);
        float wa = __int_as_float(ea.y), wb = __int_as_float(eb.y);
        acc.x += wa * va.x + wb * vb.x;
        acc.y += wa * va.y + wb * vb.y;
        acc.z += wa * va.z + wb * vb.z;
        acc.w += wa * va.w + wb * vb.w;
        if (MODE == 2) wsum += wa + wb;
    }
    for (; j < end; j += 2) {
        int jj = j + half;
        int s = 0; float w = 0.f;
        if (jj < end) { int2 e = g_csr[jj]; s = e.x; w = __int_as_float(e.y); }
        const float4 v = *(const float4*)(h + (size_t)s * NCH + q4);
        acc.x += w * v.x; acc.y += w * v.y;
        acc.z += w * v.z; acc.w += w * v.w;
        if (MODE == 2) wsum += w;
    }
    acc.x += __shfl_xor_sync(0xffffffffu, acc.x, 16);
    acc.y += __shfl_xor_sync(0xffffffffu, acc.y, 16);
    acc.z += __shfl_xor_sync(0xffffffffu, acc.z, 16);
    acc.w += __shfl_xor_sync(0xffffffffu, acc.w, 16);
    if (MODE == 2) wsum += __shfl_xor_sync(0xffffffffu, wsum, 16);

    if (half == 0) {
        float4 r;
        if (MODE == 0) {
            r = acc;
        } else if (MODE == 2) {
            // norm fused: sum_j w_j*(Y_j - m)*rstd = rstd*acc - (m*rstd)*wsum
            r.x = r4.x * acc.x - m4.x * r4.x * wsum;
            r.y = r4.y * acc.y - m4.y * r4.y * wsum;
            r.z = r4.z * acc.z - m4.z * r4.z * wsum;
            r.w = r4.w * acc.w - m4.w * r4.w * wsum;
        } else if (MODE == 1) {
            float4 s = *(const float4*)(xp + (size_t)node * NCH + q4);
            r.x = 2.0f * acc.x - s.x;
            r.y = 2.0f * acc.y - s.y;
            r.z = 2.0f * acc.z - s.z;
            r.w = 2.0f * acc.w - s.w;
        } else { // MODE 3: sub = normalized g_Y row
            float4 s = *(const float4*)(g_Y + (size_t)node * NCH + q4);
            r.x = 2.0f * acc.x - (s.x - m4.x) * r4.x;
            r.y = 2.0f * acc.y - (s.y - m4.y) * r4.y;
            r.z = 2.0f * acc.z - (s.z - m4.z) * r4.z;
            r.w = 2.0f * acc.w - (s.w - m4.w) * r4.w;
        }
        *(float4*)(o + (size_t)node * NCH + q4) = r;
    }
}

// ---------------- tf32 helpers ---------------------------------------------
__device__ __forceinline__ uint32_t f2tf(float x) {
    uint32_t r;
    asm("cvt.rna.tf32.f32 %0, %1;" : "=r"(r) : "f"(x));
    return r;
}

__device__ __forceinline__ void mma_tf32(float* c, uint32_t a0, uint32_t a1,
                                         uint32_t a2, uint32_t a3,
                                         uint32_t b0, uint32_t b1) {
    asm volatile(
        "mma.sync.aligned.m16n8k8.row.col.f32.tf32.tf32.f32 "
        "{%0,%1,%2,%3}, {%4,%5,%6,%7}, {%8,%9}, {%0,%1,%2,%3};"
        : "+f"(c[0]), "+f"(c[1]), "+f"(c[2]), "+f"(c[3])
        : "r"(a0), "r"(a1), "r"(a2), "r"(a3), "r"(b0), "r"(b1));
}

// ---------------- ChebConv GEMM (tf32) + light fused relu-stats ------------
// Y = relu([A0|Tx1|Tx2] @ W + b). Block: 128 nodes x 64 cols, K=192 (6x32).
// LAYER 1: A0 term = normalized g_Y (norm applied at staging).
#define A_P 36
#define B_P 72
template <int LAYER>
__global__ void __launch_bounds__(256)
k_gemm(const float* __restrict__ xp, const float* __restrict__ W,
       const float* __restrict__ bias) {
    __shared__ uint32_t sA[128 * A_P];     // 18432 B
    __shared__ uint32_t sB[32 * B_P];      //  9216 B

    int t = threadIdx.x;
    int lane = t & 31, wm = t >> 5;
    int gid = lane >> 2, tig = lane & 3;
    int nbase = blockIdx.x * 128;

    float acc[8][4];
#pragma unroll
    for (int nt = 0; nt < 8; nt++) {
        float b0 = __ldg(&bias[nt * 8 + 2 * tig]);
        float b1 = __ldg(&bias[nt * 8 + 2 * tig + 1]);
        acc[nt][0] = b0; acc[nt][1] = b1; acc[nt][2] = b0; acc[nt][3] = b1;
    }

#pragma unroll 1
    for (int chunk = 0; chunk < 6; chunk++) {
        int term = chunk >> 1;
        int ch0 = (chunk & 1) * 32;
        const float* A = (term == 0) ? ((LAYER == 0) ? xp : g_Y)
                                     : ((term == 1) ? g_Tx1 : g_Tx2);

#pragma unroll
        for (int i = t; i < 1024; i += 256) {
            int nn = i >> 3, q = i & 7;
            int node = nbase + nn;
            float4 v = make_float4(0.f, 0.f, 0.f, 0.f);
            if (node < NN)
                v = *(const float4*)&A[(size_t)node * NCH + ch0 + q * 4];
            if (LAYER == 1 && term == 0) {
                float4 m4 = *(const float4*)&g_stats[ch0 + q * 4];
                float4 r4 = *(const float4*)&g_stats[64 + ch0 + q * 4];
                v.x = (v.x - m4.x) * r4.x; v.y = (v.y - m4.y) * r4.y;
                v.z = (v.z - m4.z) * r4.z; v.w = (v.w - m4.w) * r4.w;
            }
            uint32_t* p = &sA[nn * A_P + q * 4];
            p[0] = f2tf(v.x); p[1] = f2tf(v.y);
            p[2] = f2tf(v.z); p[3] = f2tf(v.w);
        }
#pragma unroll
        for (int i = t; i < 512; i += 256) {
            int r = i >> 4, qc = (i & 15) * 4;
            float4 v = *(const float4*)&W[(chunk * 32 + r) * 64 + qc];
            uint32_t* p = &sB[r * B_P + qc];
            p[0] = f2tf(v.x); p[1] = f2tf(v.y);
            p[2] = f2tf(v.z); p[3] = f2tf(v.w);
        }
        __syncthreads();

#pragma unroll
        for (int ks = 0; ks < 4; ks++) {
            int k0 = ks * 8;
            int row0 = wm * 16 + gid;
            uint32_t a0 = sA[row0 * A_P + k0 + tig];
            uint32_t a1 = sA[(row0 + 8) * A_P + k0 + tig];
            uint32_t a2 = sA[row0 * A_P + k0 + tig + 4];
            uint32_t a3 = sA[(row0 + 8) * A_P + k0 + tig + 4];
#pragma unroll
            for (int nt = 0; nt < 8; nt++) {
                uint32_t b0 = sB[(k0 + tig) * B_P + nt * 8 + gid];
                uint32_t b1 = sB[(k0 + tig + 4) * B_P + nt * 8 + gid];
                mma_tf32(acc[nt], a0, a1, a2, a3, b0, b1);
            }
        }
        __syncthreads();
    }

    // relu + writeback + per-thread column partial sums
    int nr0 = nbase + wm * 16 + gid;
    int nr1 = nr0 + 8;
    bool ok0 = nr0 < NN, ok1 = nr1 < NN;
    float cs[16], cq[16];
#pragma unroll
    for (int nt = 0; nt < 8; nt++) {
        int col = nt * 8 + 2 * tig;
        float a = ok0 ? fmaxf(acc[nt][0], 0.f) : 0.f;
        float b = ok0 ? fmaxf(acc[nt][1], 0.f) : 0.f;
        float c = ok1 ? fmaxf(acc[nt][2], 0.f) : 0.f;
        float d = ok1 ? fmaxf(acc[nt][3], 0.f) : 0.f;
        if (ok0) *(float2*)&g_Y[(size_t)nr0 * NCH + col] = make_float2(a, b);
        if (ok1) *(float2*)&g_Y[(size_t)nr1 * NCH + col] = make_float2(c, d);
        cs[2 * nt]     = a + c;
        cs[2 * nt + 1] = b + d;
        cq[2 * nt]     = a * a + c * c;
        cq[2 * nt + 1] = b * b + d * d;
    }
    // reduce over gid lanes (16 rows per warp) via shfl_xor 4,8,16
#pragma unroll
    for (int m = 4; m <= 16; m <<= 1) {
#pragma unroll
        for (int i = 0; i < 16; i++) {
            cs[i] += __shfl_xor_sync(0xffffffffu, cs[i], m);
            cq[i] += __shfl_xor_sync(0xffffffffu, cq[i], m);
        }
    }
    float* ws = (float*)sB;        // 512 floats
    float* wq = ws + 512;          // 512 floats
    if (gid == 0) {
#pragma unroll
        for (int nt = 0; nt < 8; nt++) {
            ws[wm * 64 + nt * 8 + 2 * tig]     = cs[2 * nt];
            ws[wm * 64 + nt * 8 + 2 * tig + 1] = cs[2 * nt + 1];
            wq[wm * 64 + nt * 8 + 2 * tig]     = cq[2 * nt];
            wq[wm * 64 + nt * 8 + 2 * tig + 1] = cq[2 * nt + 1];
        }
    }
    __syncthreads();
    if (t < 64) {
        float S = 0.f, Q = 0.f;
#pragma unroll
        for (int w = 0; w < 8; w++) { S += ws[w * 64 + t]; Q += wq[w * 64 + t]; }
        g_part[blockIdx.x * 64 + t] = S;
        g_part[(GB + blockIdx.x) * 64 + t] = Q;
    }
}

// ---------------- stats finalize -------------------------------------------
__global__ void k_stats2() {
    __shared__ float sh[2][256];
    int c = threadIdx.x & 63, r = threadIdx.x >> 6;
    float S = 0.f, Q = 0.f;
    for (int b = r; b < GB; b += 4) {
        S += g_part[b * 64 + c];
        Q += g_part[(GB + b) * 64 + c];
    }
    sh[0][threadIdx.x] = S;
    sh[1][threadIdx.x] = Q;
    __syncthreads();
    if (threadIdx.x < 64) {
        float Sf = sh[0][c] + sh[0][c + 64] + sh[0][c + 128] + sh[0][c + 192];
        float Qf = sh[1][c] + sh[1][c + 64] + sh[1][c + 128] + sh[1][c + 192];
        float m = Sf / (float)NN;
        float var = Qf / (float)NN - m * m;
        g_stats[c] = m;
        g_stats[64 + c] = rsqrtf(var + EPS);
    }
}

// final output norm (layer 2 only)
__global__ void k_norm(float* __restrict__ outp) {
    __shared__ float sm_m[64], sm_r[64];
    if (threadIdx.x < 64) {
        sm_m[threadIdx.x] = g_stats[threadIdx.x];
        sm_r[threadIdx.x] = g_stats[64 + threadIdx.x];
    }
    __syncthreads();
    int i = blockIdx.x * blockDim.x + threadIdx.x;   // over float4 elements
    int total = NN * (NCH / 4);
    if (i < total) {
        float4 v = ((const float4*)g_Y)[i];
        int q = (i & 15) * 4;
        float4 o;
        o.x = (v.x - sm_m[q + 0]) * sm_r[q + 0];
        o.y = (v.y - sm_m[q + 1]) * sm_r[q + 1];
        o.z = (v.z - sm_m[q + 2]) * sm_r[q + 2];
        o.w = (v.w - sm_m[q + 3]) * sm_r[q + 3];
        ((float4*)outp)[i] = o;
    }
}

// ---------------- launch (kernel launches ONLY — no other CUDA APIs) -------
extern "C" void kernel_launch(void* const* d_in, const int* in_sizes, int n_in,
                              void* d_out, int out_size) {
    const float* x        = (const float*)d_in[0];
    const int* ei         = (const int*)d_in[1];
    const float* W1       = (const float*)d_in[2];
    const float* b1       = (const float*)d_in[3];
    const float* W2       = (const float*)d_in[4];
    const float* b2       = (const float*)d_in[5];
    float* out            = (float*)d_out;

    const int TB = 256;
    int nodeBlocks = (NN + TB - 1) / TB;
    int edgeBlocks = (NE + TB - 1) / TB;
    int edge4Blocks = (NE / 4 + TB - 1) / TB;
    int propBlocks = (NN + 7) / 8;
    int normBlocks = (NN * 16 + TB - 1) / TB;

    // ----- graph structure build -----
    k_zero_deg<<<nodeBlocks, TB>>>();
    k_deg<<<edge4Blocks, TB>>>(ei);
    k_scan1<<<NB1, SCAN_BLK>>>();
    k_scan2<<<1, 128>>>();
    k_scan3<<<(NN + TB - 1) / TB, TB>>>();
    k_fill<<<edgeBlocks, TB>>>(ei);

    // ----- layer 1 -----
    k_prop<0><<<propBlocks, TB>>>(x);
    k_prop<1><<<propBlocks, TB>>>(x);
    k_gemm<0><<<GB, 256>>>(x, W1, b1);
    k_stats2<<<1, 256>>>();

    // ----- layer 2 (H never materialized; norm fused into consumers) -----
    k_prop<2><<<propBlocks, TB>>>(x);
    k_prop<3><<<propBlocks, TB>>>(x);
    k_gemm<1><<<GB, 256>>>(x, W2, b2);
    k_stats2<<<1, 256>>>();
    k_norm<<<normBlocks, TB>>>(out);
}

// round 7
// speedup vs baseline: 1.0880x; 1.0880x over previous
#include <cuda_runtime.h>
#include <cstdint>

#define NN 100000
#define NE 1600000
#define NCH 64
#define EPS 1e-5f
#define SCAN_BLK 1024
#define NB1 ((NN + SCAN_BLK - 1) / SCAN_BLK)   // 98
#define GB  ((NN + 127) / 128)                 // 782 gemm blocks

// ---------------- scratch (device globals; no allocation allowed) ----------
__device__ int   g_deg[NN];
__device__ float g_dinv[NN];
__device__ int   g_off[NN + 1];
__device__ int   g_cur[NN];
__device__ int   g_bsum[NB1];
__device__ int2  g_csr[NE];                    // {src, w bits}
__device__ float g_Tx1[(size_t)NN * NCH];
__device__ float g_Tx2[(size_t)NN * NCH];
__device__ float g_Y[(size_t)NN * NCH];
__device__ float g_part[2 * GB * NCH];
__device__ float g_stats[2 * NCH];

// ---------------- degree ---------------------------------------------------
__global__ void k_zero_deg() {
    int i = blockIdx.x * blockDim.x + threadIdx.x;
    if (i < NN) g_deg[i] = 0;
}

// edge_index is int32 (JAX default x64-disabled demotes int64 -> int32)
__global__ void k_deg(const int* __restrict__ ei) {
    int i = blockIdx.x * blockDim.x + threadIdx.x;
    if (i < NE / 4) {
        int4 d = ((const int4*)(ei + NE))[i];
        if ((unsigned)d.x < NN) atomicAdd(&g_deg[d.x], 1);
        if ((unsigned)d.y < NN) atomicAdd(&g_deg[d.y], 1);
        if ((unsigned)d.z < NN) atomicAdd(&g_deg[d.z], 1);
        if ((unsigned)d.w < NN) atomicAdd(&g_deg[d.w], 1);
    }
}

// ---------------- prefix sum (3-phase), dinv fused into phase 1 ------------
__global__ void k_scan1() {
    __shared__ int sh[SCAN_BLK];
    int tid = threadIdx.x;
    int i = blockIdx.x * SCAN_BLK + tid;
    int v = 0;
    if (i < NN) {
        v = g_deg[i];
        g_dinv[i] = (v > 0) ? rsqrtf((float)v) : 0.0f;
    }
    sh[tid] = v;
    __syncthreads();
    for (int ofs = 1; ofs < SCAN_BLK; ofs <<= 1) {
        int t = (tid >= ofs) ? sh[tid - ofs] : 0;
        __syncthreads();
        sh[tid] += t;
        __syncthreads();
    }
    if (i < NN) g_off[i + 1] = sh[tid];       // local inclusive
    if (tid == SCAN_BLK - 1) g_bsum[blockIdx.x] = sh[tid];
}

// parallel exclusive scan over NB1 (=98) block sums
__global__ void k_scan2() {
    __shared__ int sh[128];
    int tid = threadIdx.x;
    int v = (tid < NB1) ? g_bsum[tid] : 0;
    sh[tid] = v;
    __syncthreads();
    for (int ofs = 1; ofs < 128; ofs <<= 1) {
        int t = (tid >= ofs) ? sh[tid - ofs] : 0;
        __syncthreads();
        sh[tid] += t;
        __syncthreads();
    }
    if (tid < NB1) g_bsum[tid] = sh[tid] - v; // exclusive
}

// phase 3 + cur init fused
__global__ void k_scan3() {
    int i = blockIdx.x * blockDim.x + threadIdx.x;
    if (i < NN) {
        int fin = g_off[i + 1] + g_bsum[i / SCAN_BLK];
        g_off[i + 1] = fin;
        if (i + 1 < NN) g_cur[i + 1] = fin;
    }
    if (i == 0) { g_off[0] = 0; g_cur[0] = 0; }
}

// ---------------- counting-sort edges into CSR by dst (2 edges/thread) -----
__global__ void k_fill(const int* __restrict__ ei) {
    int i = blockIdx.x * blockDim.x + threadIdx.x;
    if (i < NE / 2) {
        int2 s2 = ((const int2*)ei)[i];
        int2 d2 = ((const int2*)(ei + NE))[i];
        if ((unsigned)s2.x < NN && (unsigned)d2.x < NN) {
            float w = -g_dinv[s2.x] * g_dinv[d2.x];
            int pos = atomicAdd(&g_cur[d2.x], 1);
            if ((unsigned)pos < NE)
                g_csr[pos] = make_int2(s2.x, __float_as_int(w));
        }
        if ((unsigned)s2.y < NN && (unsigned)d2.y < NN) {
            float w = -g_dinv[s2.y] * g_dinv[d2.y];
            int pos = atomicAdd(&g_cur[d2.y], 1);
            if ((unsigned)pos < NE)
                g_csr[pos] = make_int2(s2.y, __float_as_int(w));
        }
    }
}

// ---------------- sparse propagation: one warp per dst node ----------------
// Half-warp per edge; lane covers 16B (float4) of the 256B row.
// MODE 0: h=xp,  o=Tx1                MODE 1: h=Tx1, o=Tx2, sub=xp
// MODE 2: h=norm(g_Y), o=Tx1          MODE 3: h=Tx1, o=Tx2, sub=norm(g_Y)
template <int MODE>
__global__ void k_prop(const float* __restrict__ xp) {
    const float* h;
    float* o;
    if (MODE == 0) { h = xp;    o = g_Tx1; }
    if (MODE == 1) { h = g_Tx1; o = g_Tx2; }
    if (MODE == 2) { h = g_Y;   o = g_Tx1; }
    if (MODE == 3) { h = g_Tx1; o = g_Tx2; }

    int node = blockIdx.x * (blockDim.x >> 5) + (threadIdx.x >> 5);
    if (node >= NN) return;
    int lane = threadIdx.x & 31;
    int half = lane >> 4;
    int q4 = (lane & 15) * 4;
    int beg = g_off[node], end = g_off[node + 1];

    float4 m4, r4;
    if (MODE == 2 || MODE == 3) {
        m4 = *(const float4*)(g_stats + q4);
        r4 = *(const float4*)(g_stats + 64 + q4);
    }

    float4 acc = make_float4(0.f, 0.f, 0.f, 0.f);
    float wsum = 0.f;
    int j = beg;
    for (; j + 7 < end; j += 8) {
        int2 ea = g_csr[j + half];
        int2 eb = g_csr[j + 2 + half];
        int2 ec = g_csr[j + 4 + half];
        int2 ed = g_csr[j + 6 + half];
        const float4 va = *(const float4*)(h + (size_t)ea.x * NCH + q4);
        const float4 vb = *(const float4*)(h + (size_t)eb.x * NCH + q4);
        const float4 vc = *(const float4*)(h + (size_t)ec.x * NCH + q4);
        const float4 vd = *(const float4*)(h + (size_t)ed.x * NCH + q4);
        float wa = __int_as_float(ea.y), wb = __int_as_float(eb.y);
        float wc = __int_as_float(ec.y), wd = __int_as_float(ed.y);
        acc.x += wa * va.x + wb * vb.x + wc * vc.x + wd * vd.x;
        acc.y += wa * va.y + wb * vb.y + wc * vc.y + wd * vd.y;
        acc.z += wa * va.z + wb * vb.z + wc * vc.z + wd * vd.z;
        acc.w += wa * va.w + wb * vb.w + wc * vc.w + wd * vd.w;
        if (MODE == 2) wsum += wa + wb + wc + wd;
    }
    for (; j + 3 < end; j += 4) {
        int2 ea = g_csr[j + half];
        int2 eb = g_csr[j + 2 + half];
        const float4 va = *(const float4*)(h + (size_t)ea.x * NCH + q4);
        const float4 vb = *(const float4*)(h + (size_t)eb.x * NCH + q4);
        float wa = __int_as_float(ea.y), wb = __int_as_float(eb.y);
        acc.x += wa * va.x + wb * vb.x;
        acc.y += wa * va.y + wb * vb.y;
        acc.z += wa * va.z + wb * vb.z;
        acc.w += wa * va.w + wb * vb.w;
        if (MODE == 2) wsum += wa + wb;
    }
    for (; j < end; j += 2) {
        int jj = j + half;
        int s = 0; float w = 0.f;
        if (jj < end) { int2 e = g_csr[jj]; s = e.x; w = __int_as_float(e.y); }
        const float4 v = *(const float4*)(h + (size_t)s * NCH + q4);
        acc.x += w * v.x; acc.y += w * v.y;
        acc.z += w * v.z; acc.w += w * v.w;
        if (MODE == 2) wsum += w;
    }
    acc.x += __shfl_xor_sync(0xffffffffu, acc.x, 16);
    acc.y += __shfl_xor_sync(0xffffffffu, acc.y, 16);
    acc.z += __shfl_xor_sync(0xffffffffu, acc.z, 16);
    acc.w += __shfl_xor_sync(0xffffffffu, acc.w, 16);
    if (MODE == 2) wsum += __shfl_xor_sync(0xffffffffu, wsum, 16);

    if (half == 0) {
        float4 r;
        if (MODE == 0) {
            r = acc;
        } else if (MODE == 2) {
            r.x = r4.x * acc.x - m4.x * r4.x * wsum;
            r.y = r4.y * acc.y - m4.y * r4.y * wsum;
            r.z = r4.z * acc.z - m4.z * r4.z * wsum;
            r.w = r4.w * acc.w - m4.w * r4.w * wsum;
        } else if (MODE == 1) {
            float4 s = *(const float4*)(xp + (size_t)node * NCH + q4);
            r.x = 2.0f * acc.x - s.x;
            r.y = 2.0f * acc.y - s.y;
            r.z = 2.0f * acc.z - s.z;
            r.w = 2.0f * acc.w - s.w;
        } else { // MODE 3
            float4 s = *(const float4*)(g_Y + (size_t)node * NCH + q4);
            r.x = 2.0f * acc.x - (s.x - m4.x) * r4.x;
            r.y = 2.0f * acc.y - (s.y - m4.y) * r4.y;
            r.z = 2.0f * acc.z - (s.z - m4.z) * r4.z;
            r.w = 2.0f * acc.w - (s.w - m4.w) * r4.w;
        }
        *(float4*)(o + (size_t)node * NCH + q4) = r;
    }
}

// ---------------- tf32 helpers ---------------------------------------------
__device__ __forceinline__ uint32_t f2tf(float x) {
    uint32_t r;
    asm("cvt.rna.tf32.f32 %0, %1;" : "=r"(r) : "f"(x));
    return r;
}

__device__ __forceinline__ void mma_tf32(float* c, uint32_t a0, uint32_t a1,
                                         uint32_t a2, uint32_t a3,
                                         uint32_t b0, uint32_t b1) {
    asm volatile(
        "mma.sync.aligned.m16n8k8.row.col.f32.tf32.tf32.f32 "
        "{%0,%1,%2,%3}, {%4,%5,%6,%7}, {%8,%9}, {%0,%1,%2,%3};"
        : "+f"(c[0]), "+f"(c[1]), "+f"(c[2]), "+f"(c[3])
        : "r"(a0), "r"(a1), "r"(a2), "r"(a3), "r"(b0), "r"(b1));
}

// ---------------- ChebConv GEMM (tf32) + fused relu-stats ------------------
// Y = relu([A0|Tx1|Tx2] @ W + b). Block: 128 nodes x 64 cols, K=192 (6x32).
// LAYER 1: A0 term = normalized g_Y (norm applied at staging).
// Epilogue: per-nt shfl reduction (low register pressure, no spills).
#define A_P 36
#define B_P 72
template <int LAYER>
__global__ void __launch_bounds__(256)
k_gemm(const float* __restrict__ xp, const float* __restrict__ W,
       const float* __restrict__ bias) {
    __shared__ uint32_t sA[128 * A_P];     // 18432 B
    __shared__ uint32_t sB[32 * B_P];      //  9216 B

    int t = threadIdx.x;
    int lane = t & 31, wm = t >> 5;
    int gid = lane >> 2, tig = lane & 3;
    int nbase = blockIdx.x * 128;

    float acc[8][4];
#pragma unroll
    for (int nt = 0; nt < 8; nt++) {
        float b0 = __ldg(&bias[nt * 8 + 2 * tig]);
        float b1 = __ldg(&bias[nt * 8 + 2 * tig + 1]);
        acc[nt][0] = b0; acc[nt][1] = b1; acc[nt][2] = b0; acc[nt][3] = b1;
    }

#pragma unroll 1
    for (int chunk = 0; chunk < 6; chunk++) {
        int term = chunk >> 1;
        int ch0 = (chunk & 1) * 32;
        const float* A = (term == 0) ? ((LAYER == 0) ? xp : g_Y)
                                     : ((term == 1) ? g_Tx1 : g_Tx2);

#pragma unroll
        for (int i = t; i < 1024; i += 256) {
            int nn = i >> 3, q = i & 7;
            int node = nbase + nn;
            float4 v = make_float4(0.f, 0.f, 0.f, 0.f);
            if (node < NN)
                v = *(const float4*)&A[(size_t)node * NCH + ch0 + q * 4];
            if (LAYER == 1 && term == 0) {
                float4 m4 = *(const float4*)&g_stats[ch0 + q * 4];
                float4 r4 = *(const float4*)&g_stats[64 + ch0 + q * 4];
                v.x = (v.x - m4.x) * r4.x; v.y = (v.y - m4.y) * r4.y;
                v.z = (v.z - m4.z) * r4.z; v.w = (v.w - m4.w) * r4.w;
            }
            uint32_t* p = &sA[nn * A_P + q * 4];
            p[0] = f2tf(v.x); p[1] = f2tf(v.y);
            p[2] = f2tf(v.z); p[3] = f2tf(v.w);
        }
#pragma unroll
        for (int i = t; i < 512; i += 256) {
            int r = i >> 4, qc = (i & 15) * 4;
            float4 v = *(const float4*)&W[(chunk * 32 + r) * 64 + qc];
            uint32_t* p = &sB[r * B_P + qc];
            p[0] = f2tf(v.x); p[1] = f2tf(v.y);
            p[2] = f2tf(v.z); p[3] = f2tf(v.w);
        }
        __syncthreads();

#pragma unroll
        for (int ks = 0; ks < 4; ks++) {
            int k0 = ks * 8;
            int row0 = wm * 16 + gid;
            uint32_t a0 = sA[row0 * A_P + k0 + tig];
            uint32_t a1 = sA[(row0 + 8) * A_P + k0 + tig];
            uint32_t a2 = sA[row0 * A_P + k0 + tig + 4];
            uint32_t a3 = sA[(row0 + 8) * A_P + k0 + tig + 4];
#pragma unroll
            for (int nt = 0; nt < 8; nt++) {
                uint32_t b0 = sB[(k0 + tig) * B_P + nt * 8 + gid];
                uint32_t b1 = sB[(k0 + tig + 4) * B_P + nt * 8 + gid];
                mma_tf32(acc[nt], a0, a1, a2, a3, b0, b1);
            }
        }
        __syncthreads();
    }

    // relu + writeback + per-nt stats reduction (4 live scalars at a time)
    int nr0 = nbase + wm * 16 + gid;
    int nr1 = nr0 + 8;
    bool ok0 = nr0 < NN, ok1 = nr1 < NN;
    float* ws = (float*)sB;        // 512 floats (sB free after mainloop)
    float* wq = ws + 512;          // 512 floats
#pragma unroll
    for (int nt = 0; nt < 8; nt++) {
        int col = nt * 8 + 2 * tig;
        float a = ok0 ? fmaxf(acc[nt][0], 0.f) : 0.f;
        float b = ok0 ? fmaxf(acc[nt][1], 0.f) : 0.f;
        float c = ok1 ? fmaxf(acc[nt][2], 0.f) : 0.f;
        float d = ok1 ? fmaxf(acc[nt][3], 0.f) : 0.f;
        if (ok0) *(float2*)&g_Y[(size_t)nr0 * NCH + col] = make_float2(a, b);
        if (ok1) *(float2*)&g_Y[(size_t)nr1 * NCH + col] = make_float2(c, d);
        float s0 = a + c, s1 = b + d;
        float q0 = a * a + c * c, q1 = b * b + d * d;
#pragma unroll
        for (int m = 4; m <= 16; m <<= 1) {
            s0 += __shfl_xor_sync(0xffffffffu, s0, m);
            s1 += __shfl_xor_sync(0xffffffffu, s1, m);
            q0 += __shfl_xor_sync(0xffffffffu, q0, m);
            q1 += __shfl_xor_sync(0xffffffffu, q1, m);
        }
        if (gid == 0) {
            ws[wm * 64 + col]     = s0;
            ws[wm * 64 + col + 1] = s1;
            wq[wm * 64 + col]     = q0;
            wq[wm * 64 + col + 1] = q1;
        }
    }
    __syncthreads();
    if (t < 64) {
        float S = 0.f, Q = 0.f;
#pragma unroll
        for (int w = 0; w < 8; w++) { S += ws[w * 64 + t]; Q += wq[w * 64 + t]; }
        g_part[blockIdx.x * 64 + t] = S;
        g_part[(GB + blockIdx.x) * 64 + t] = Q;
    }
}

// ---------------- stats finalize (1024 threads for MLP) --------------------
__global__ void k_stats2() {
    __shared__ float sh[2][1024];
    int c = threadIdx.x & 63, r = threadIdx.x >> 6;   // 16 groups
    float S = 0.f, Q = 0.f;
    for (int b = r; b < GB; b += 16) {
        S += g_part[b * 64 + c];
        Q += g_part[(GB + b) * 64 + c];
    }
    sh[0][threadIdx.x] = S;
    sh[1][threadIdx.x] = Q;
    __syncthreads();
    if (threadIdx.x < 64) {
        float Sf = 0.f, Qf = 0.f;
#pragma unroll
        for (int g = 0; g < 16; g++) {
            Sf += sh[0][g * 64 + c];
            Qf += sh[1][g * 64 + c];
        }
        float m = Sf / (float)NN;
        float var = Qf / (float)NN - m * m;
        g_stats[c] = m;
        g_stats[64 + c] = rsqrtf(var + EPS);
    }
}

// final output norm (layer 2 only)
__global__ void k_norm(float* __restrict__ outp) {
    __shared__ float sm_m[64], sm_r[64];
    if (threadIdx.x < 64) {
        sm_m[threadIdx.x] = g_stats[threadIdx.x];
        sm_r[threadIdx.x] = g_stats[64 + threadIdx.x];
    }
    __syncthreads();
    int i = blockIdx.x * blockDim.x + threadIdx.x;
    int total = NN * (NCH / 4);
    if (i < total) {
        float4 v = ((const float4*)g_Y)[i];
        int q = (i & 15) * 4;
        float4 o;
        o.x = (v.x - sm_m[q + 0]) * sm_r[q + 0];
        o.y = (v.y - sm_m[q + 1]) * sm_r[q + 1];
        o.z = (v.z - sm_m[q + 2]) * sm_r[q + 2];
        o.w = (v.w - sm_m[q + 3]) * sm_r[q + 3];
        ((float4*)outp)[i] = o;
    }
}

// ---------------- launch (kernel launches ONLY — no other CUDA APIs) -------
extern "C" void kernel_launch(void* const* d_in, const int* in_sizes, int n_in,
                              void* d_out, int out_size) {
    const float* x        = (const float*)d_in[0];
    const int* ei         = (const int*)d_in[1];
    const float* W1       = (const float*)d_in[2];
    const float* b1       = (const float*)d_in[3];
    const float* W2       = (const float*)d_in[4];
    const float* b2       = (const float*)d_in[5];
    float* out            = (float*)d_out;

    const int TB = 256;
    int nodeBlocks = (NN + TB - 1) / TB;
    int edge4Blocks = (NE / 4 + TB - 1) / TB;
    int edge2Blocks = (NE / 2 + TB - 1) / TB;
    int propBlocks = (NN + 7) / 8;
    int normBlocks = (NN * 16 + TB - 1) / TB;

    // ----- graph structure build -----
    k_zero_deg<<<nodeBlocks, TB>>>();
    k_deg<<<edge4Blocks, TB>>>(ei);
    k_scan1<<<NB1, SCAN_BLK>>>();
    k_scan2<<<1, 128>>>();
    k_scan3<<<(NN + TB - 1) / TB, TB>>>();
    k_fill<<<edge2Blocks, TB>>>(ei);

    // ----- layer 1 -----
    k_prop<0><<<propBlocks, TB>>>(x);
    k_prop<1><<<propBlocks, TB>>>(x);
    k_gemm<0><<<GB, 256>>>(x, W1, b1);
    k_stats2<<<1, 1024>>>();

    // ----- layer 2 (H never materialized; norm fused into consumers) -----
    k_prop<2><<<propBlocks, TB>>>(x);
    k_prop<3><<<propBlocks, TB>>>(x);
    k_gemm<1><<<GB, 256>>>(x, W2, b2);
    k_stats2<<<1, 1024>>>();
    k_norm<<<normBlocks, TB>>>(out);
}